// round 14
// baseline (speedup 1.0000x reference)
#include <cuda_runtime.h>
#include <cuda_bf16.h>
#include <math.h>
#include <stdint.h>

#define NN 100000
#define NE 1600000
#define H  128
#define NG 128
#define NB1 391          // ceil(NN/256)

// ---------------- scratch (device globals) ----------------------------------
__device__ uint32_t d_hhi[(size_t)NN * 64];    // h as bf16 pairs (hi/lo split)
__device__ uint32_t d_hlo[(size_t)NN * 64];
__device__ uint32_t d_ahi[(size_t)NN * 64];    // agg hi/lo
__device__ uint32_t d_alo[(size_t)NN * 64];
__device__ float    d_srz[(size_t)NN * 256];   // i_r+h_r | i_z+h_z (biased)
__device__ float    d_gin[(size_t)NN * 128];   // i_n + bih_n
__device__ float    d_ghn[(size_t)NN * 128];   // h_n + bhh_n
__device__ float    d_gmax[(size_t)NG * H];
// CSR
__device__ int d_cnt[NN];
__device__ int d_rowptr[NN + 1];
__device__ int d_pos[NN];
__device__ int d_esrc[NE];
__device__ int d_bsum[512];
__device__ int d_boff[512];
// pre-split weights: rows 0-383 Wih0, 384-767 Whh0, 768-1151 Wih1,
// 1152-1535 Whh1, 1536-1663 dense
#define WROWS 1664
__device__ __nv_bfloat16 d_whi[(size_t)WROWS * 128];
__device__ __nv_bfloat16 d_wlo[(size_t)WROWS * 128];

// ---------------- helpers ----------------------------------------------------
__device__ __forceinline__ uint32_t smem_u32(const void* p) {
    uint32_t a;
    asm("{ .reg .u64 t; cvta.to.shared.u64 t, %1; cvt.u32.u64 %0, t; }"
        : "=r"(a) : "l"(p));
    return a;
}
#define LDSM_X4(r0, r1, r2, r3, addr)                                       \
    asm volatile("ldmatrix.sync.aligned.m8n8.x4.shared.b16 {%0,%1,%2,%3}, [%4];" \
        : "=r"(r0), "=r"(r1), "=r"(r2), "=r"(r3) : "r"(addr))
#define MMA_BF16(c, a0, a1, a2, a3, b0, b1)                                 \
    asm volatile("mma.sync.aligned.m16n8k16.row.col.f32.bf16.bf16.f32 "     \
        "{%0,%1,%2,%3}, {%4,%5,%6,%7}, {%8,%9}, {%0,%1,%2,%3};"             \
        : "+f"((c)[0]), "+f"((c)[1]), "+f"((c)[2]), "+f"((c)[3])            \
        : "r"(a0), "r"(a1), "r"(a2), "r"(a3), "r"(b0), "r"(b1))
#define CP16(dst, src)                                                      \
    asm volatile("cp.async.cg.shared.global [%0], [%1], 16;"                \
                 :: "r"(dst), "l"(src))
#define CP_COMMIT asm volatile("cp.async.commit_group;")
#define CP_WAIT0  asm volatile("cp.async.wait_group 0;" ::: "memory")
#define NEG_INF __int_as_float(0xFF800000)

__device__ __forceinline__ float sigm(float x) {
    return 1.f / (1.f + __expf(-x));
}
// tanh(x) = 1 - 2/(e^{2x}+1); exact saturation at +-inf, err ~1e-6
__device__ __forceinline__ float tanh_fast(float x) {
    float e = __expf(2.f * x);
    return 1.f - __fdividef(2.f, e + 1.f);
}

// split float4 -> bf16 hi/lo pairs
__device__ __forceinline__ void split_store(float4 a, uint32_t* hip, uint32_t* lop) {
    __nv_bfloat162 h01 = __floats2bfloat162_rn(a.x, a.y);
    float2 f01 = __bfloat1622float2(h01);
    __nv_bfloat162 l01 = __floats2bfloat162_rn(a.x - f01.x, a.y - f01.y);
    __nv_bfloat162 h23 = __floats2bfloat162_rn(a.z, a.w);
    float2 f23 = __bfloat1622float2(h23);
    __nv_bfloat162 l23 = __floats2bfloat162_rn(a.z - f23.x, a.w - f23.y);
    *(uint2*)hip = make_uint2(*(uint32_t*)&h01, *(uint32_t*)&h23);
    *(uint2*)lop = make_uint2(*(uint32_t*)&l01, *(uint32_t*)&l23);
}
// reconstruct 4 floats from hi/lo pairs
__device__ __forceinline__ float4 h_rec(const uint32_t* hip, const uint32_t* lop) {
    uint2 vh = *(const uint2*)hip;
    uint2 vl = *(const uint2*)lop;
    float2 h01 = __bfloat1622float2(*(__nv_bfloat162*)&vh.x);
    float2 h23 = __bfloat1622float2(*(__nv_bfloat162*)&vh.y);
    float2 l01 = __bfloat1622float2(*(__nv_bfloat162*)&vl.x);
    float2 l23 = __bfloat1622float2(*(__nv_bfloat162*)&vl.y);
    return make_float4(h01.x + l01.x, h01.y + l01.y, h23.x + l23.x, h23.y + l23.y);
}

// ---------------- weight pre-split ------------------------------------------
__global__ void conv_weights(const float* __restrict__ Wih0, const float* __restrict__ Whh0,
                             const float* __restrict__ Wih1, const float* __restrict__ Whh1,
                             const float* __restrict__ denseW) {
    int idx = blockIdx.x * blockDim.x + threadIdx.x;
    if (idx >= WROWS * 128) return;
    int row = idx >> 7, col = idx & 127;
    float v;
    if      (row < 384)  v = Wih0[row * 128 + col];
    else if (row < 768)  v = Whh0[(row - 384) * 128 + col];
    else if (row < 1152) v = Wih1[(row - 768) * 128 + col];
    else if (row < 1536) v = Whh1[(row - 1152) * 128 + col];
    else                 v = denseW[(row - 1536) * 128 + col];
    __nv_bfloat16 h = __float2bfloat16(v);
    d_whi[idx] = h;
    d_wlo[idx] = __float2bfloat16(v - __bfloat162float(h));
}

// ---------------- gather: h = emb[x] (split only) ---------------------------
__global__ void gather_embed(const int* __restrict__ x,
                             const float* __restrict__ emb) {
    int idx = blockIdx.x * blockDim.x + threadIdx.x;
    if (idx >= NN * 32) return;
    int n = idx >> 5, c = idx & 31;
    int tok = x[n];
    float4 v = *(const float4*)&emb[(size_t)tok * H + c * 4];
    split_store(v, &d_hhi[(size_t)n * 64 + c * 2], &d_hlo[(size_t)n * 64 + c * 2]);
}

// ---------------- CSR build --------------------------------------------------
__global__ void csr_zero() {
    int i = blockIdx.x * blockDim.x + threadIdx.x;
    if (i < NN) d_cnt[i] = 0;
}
__global__ void csr_hist(const int* __restrict__ ei) {
    int e = blockIdx.x * blockDim.x + threadIdx.x;
    if (e < NE) atomicAdd(&d_cnt[ei[NE + e]], 1);
}
__global__ void csr_bsum() {
    int tid = threadIdx.x, idx = blockIdx.x * 256 + tid;
    int v = (idx < NN) ? d_cnt[idx] : 0;
    #pragma unroll
    for (int o = 16; o > 0; o >>= 1) v += __shfl_down_sync(0xffffffffu, v, o);
    __shared__ int ws[8];
    if ((tid & 31) == 0) ws[tid >> 5] = v;
    __syncthreads();
    if (tid == 0) {
        int s = 0;
        #pragma unroll
        for (int i = 0; i < 8; i++) s += ws[i];
        d_bsum[blockIdx.x] = s;
    }
}
__global__ void csr_bscan() {
    __shared__ int s[512];
    int t = threadIdx.x;
    int v = (t < NB1) ? d_bsum[t] : 0;
    s[t] = v; __syncthreads();
    for (int o = 1; o < 512; o <<= 1) {
        int x = (t >= o) ? s[t - o] : 0;
        __syncthreads();
        s[t] += x;
        __syncthreads();
    }
    d_boff[t] = s[t] - v;
    if (t == 0) d_rowptr[NN] = NE;
}
__global__ void csr_write() {
    int tid = threadIdx.x, lane = tid & 31, wid = tid >> 5;
    int idx = blockIdx.x * 256 + tid;
    int v = (idx < NN) ? d_cnt[idx] : 0;
    int incl = v;
    #pragma unroll
    for (int o = 1; o < 32; o <<= 1) {
        int y = __shfl_up_sync(0xffffffffu, incl, o);
        if (lane >= o) incl += y;
    }
    __shared__ int ws[8];
    if (lane == 31) ws[wid] = incl;
    __syncthreads();
    if (tid < 8) {
        int x = ws[tid];
        #pragma unroll
        for (int o = 1; o < 8; o <<= 1) {
            int y = __shfl_up_sync(0xffu, x, o);
            if (tid >= o) x += y;
        }
        ws[tid] = x;
    }
    __syncthreads();
    int base = d_boff[blockIdx.x] + (wid ? ws[wid - 1] : 0);
    int excl = base + incl - v;
    if (idx < NN) { d_rowptr[idx] = excl; d_pos[idx] = excl; }
}
__global__ void csr_fill(const int* __restrict__ ei) {
    int e = blockIdx.x * blockDim.x + threadIdx.x;
    if (e >= NE) return;
    int dst = ei[NE + e];
    int p = atomicAdd(&d_pos[dst], 1);
    d_esrc[p] = ei[e];
}

// ---------------- agg = segment_sum(h[src]) -> bf16 hi/lo -------------------
__global__ void agg_gather() {          // one warp per node
    int gw = (blockIdx.x * blockDim.x + threadIdx.x) >> 5;
    if (gw >= NN) return;
    int lane = threadIdx.x & 31;
    int beg = d_rowptr[gw], end = d_rowptr[gw + 1];
    float4 a0 = make_float4(0.f, 0.f, 0.f, 0.f);
    float4 a1 = make_float4(0.f, 0.f, 0.f, 0.f);
    int i = beg;
    for (; i + 1 < end; i += 2) {
        int s0 = __ldg(&d_esrc[i]), s1 = __ldg(&d_esrc[i + 1]);
        float4 v0 = h_rec(&d_hhi[(size_t)s0 * 64 + lane * 2], &d_hlo[(size_t)s0 * 64 + lane * 2]);
        float4 v1 = h_rec(&d_hhi[(size_t)s1 * 64 + lane * 2], &d_hlo[(size_t)s1 * 64 + lane * 2]);
        a0.x += v0.x; a0.y += v0.y; a0.z += v0.z; a0.w += v0.w;
        a1.x += v1.x; a1.y += v1.y; a1.z += v1.z; a1.w += v1.w;
    }
    if (i < end) {
        int s0 = __ldg(&d_esrc[i]);
        float4 v0 = h_rec(&d_hhi[(size_t)s0 * 64 + lane * 2], &d_hlo[(size_t)s0 * 64 + lane * 2]);
        a0.x += v0.x; a0.y += v0.y; a0.z += v0.z; a0.w += v0.w;
    }
    a0.x += a1.x; a0.y += a1.y; a0.z += a1.z; a0.w += a1.w;
    split_store(a0, &d_ahi[(size_t)gw * 64 + lane * 2], &d_alo[(size_t)gw * 64 + lane * 2]);
}

// ======================= dual GEMM: BM=128, BN=128, 512 thr ==================
// smem: Ahi 32K | Alo 32K | Bhi 32K | Blo 32K = 128KB, 1 CTA/SM (16 warps).
// Warp grid 4(m) x 4(n); warp tile 32x32 (per-thread regs unchanged).
// grid.y = 3: bt=0 -> r gate, bt=1 -> z gate, bt=2 -> n gate.
#define D_AHI  0
#define D_ALO  32768
#define D_BHI  65536
#define D_BLO  98304
#define DUAL_SMEM 131072

__device__ __forceinline__ void tile_load512(uint32_t sb, char* smem,
    const __nv_bfloat16* __restrict__ Ahi, const __nv_bfloat16* __restrict__ Alo,
    const __nv_bfloat16* __restrict__ Whi, const __nv_bfloat16* __restrict__ Wlo,
    int bm, int bn, int M, int tid)
{
    #pragma unroll
    for (int it = 0; it < 4; it++) {
        int p = tid + it * 512;            // 2048 A slots
        int row = p >> 4, c8 = p & 15;
        uint32_t off = row * 256 + ((c8 ^ (row & 7)) << 4);
        int m = bm + row;
        if (m < M) {
            CP16(sb + D_AHI + off, Ahi + (size_t)m * 128 + c8 * 8);
            CP16(sb + D_ALO + off, Alo + (size_t)m * 128 + c8 * 8);
        } else {
            *(uint4*)(smem + D_AHI + off) = make_uint4(0, 0, 0, 0);
            *(uint4*)(smem + D_ALO + off) = make_uint4(0, 0, 0, 0);
        }
    }
    #pragma unroll
    for (int it = 0; it < 4; it++) {
        int p = tid + it * 512;            // 2048 B slots (128 rows)
        int row = p >> 4, c8 = p & 15;
        uint32_t off = row * 256 + ((c8 ^ (row & 7)) << 4);
        CP16(sb + D_BHI + off, Whi + (size_t)(bn + row) * 128 + c8 * 8);
        CP16(sb + D_BLO + off, Wlo + (size_t)(bn + row) * 128 + c8 * 8);
    }
    CP_COMMIT;
    CP_WAIT0;
}

__device__ __forceinline__ void tile_compute512(uint32_t sb, float acc[2][4][4],
                                                int wm, int wn, int lrow, int lc)
{
    #pragma unroll
    for (int ks = 0; ks < 8; ks++) {
        const int cidx = 2 * ks + lc;
        uint32_t ah[2][4], al[2][4], bh[2][4], bl[2][4];
        #pragma unroll
        for (int tm = 0; tm < 2; tm++) {
            int r = wm * 32 + tm * 16 + lrow;
            uint32_t off = r * 256 + ((cidx ^ (r & 7)) << 4);
            LDSM_X4(ah[tm][0], ah[tm][1], ah[tm][2], ah[tm][3], sb + D_AHI + off);
            LDSM_X4(al[tm][0], al[tm][1], al[tm][2], al[tm][3], sb + D_ALO + off);
        }
        #pragma unroll
        for (int u = 0; u < 2; u++) {
            int r = wn * 32 + u * 16 + lrow;
            uint32_t off = r * 256 + ((cidx ^ (r & 7)) << 4);
            LDSM_X4(bh[u][0], bh[u][1], bh[u][2], bh[u][3], sb + D_BHI + off);
            LDSM_X4(bl[u][0], bl[u][1], bl[u][2], bl[u][3], sb + D_BLO + off);
        }
        #pragma unroll
        for (int tm = 0; tm < 2; tm++)
            #pragma unroll
            for (int tn = 0; tn < 4; tn++) {
                int u = tn >> 1, s = tn & 1;
                MMA_BF16(acc[tm][tn], ah[tm][0], ah[tm][1], ah[tm][2], ah[tm][3],
                         bh[u][s], bh[u][2 + s]);
                MMA_BF16(acc[tm][tn], ah[tm][0], ah[tm][1], ah[tm][2], ah[tm][3],
                         bl[u][s], bl[u][2 + s]);
                MMA_BF16(acc[tm][tn], al[tm][0], al[tm][1], al[tm][2], al[tm][3],
                         bh[u][s], bh[u][2 + s]);
            }
    }
}

__global__ void __launch_bounds__(512, 1)
gemm_dual(const __nv_bfloat16* __restrict__ Aihi, const __nv_bfloat16* __restrict__ Ailo,
          const __nv_bfloat16* __restrict__ Wihi, const __nv_bfloat16* __restrict__ Wilo,
          const __nv_bfloat16* __restrict__ Ahhi, const __nv_bfloat16* __restrict__ Ahlo,
          const __nv_bfloat16* __restrict__ Whhi, const __nv_bfloat16* __restrict__ Whlo,
          const float* __restrict__ bih, const float* __restrict__ bhh,
          float* __restrict__ srz, float* __restrict__ gin, float* __restrict__ ghn,
          int M)
{
    extern __shared__ char smem[];
    const uint32_t sb = smem_u32(smem);
    const int tid = threadIdx.x, wid = tid >> 5, lane = tid & 31;
    const int bm = blockIdx.x * 128;
    const int bt = blockIdx.y, bn = bt * 128;   // gate tile: full 128 cols
    const int wm = wid & 3, wn = wid >> 2;      // 4 x 4 warps
    const int lrow = lane & 15, lc = lane >> 4;

    float acc_i[2][4][4], acc_h[2][4][4];
    #pragma unroll
    for (int i = 0; i < 2; i++)
        #pragma unroll
        for (int j = 0; j < 4; j++)
            #pragma unroll
            for (int q = 0; q < 4; q++) { acc_i[i][j][q] = 0.f; acc_h[i][j][q] = 0.f; }

    tile_load512(sb, smem, Aihi, Ailo, Wihi, Wilo, bm, bn, M, tid);
    __syncthreads();
    tile_compute512(sb, acc_i, wm, wn, lrow, lc);
    __syncthreads();
    tile_load512(sb, smem, Ahhi, Ahlo, Whhi, Whlo, bm, bn, M, tid);
    __syncthreads();
    tile_compute512(sb, acc_h, wm, wn, lrow, lc);

    // ---- epilogue ----
    const int g = lane >> 2, q = lane & 3;
    if (bt < 2) {                            // r (bt=0) / z (bt=1): write summed
        #pragma unroll
        for (int tn = 0; tn < 4; tn++) {
            int cl = wn * 32 + tn * 8 + q * 2;     // 0..127
            int ng = bn + cl;                       // global gate col
            float2 b2 = make_float2(bih[ng] + bhh[ng], bih[ng + 1] + bhh[ng + 1]);
            #pragma unroll
            for (int tm = 0; tm < 2; tm++) {
                int m0 = bm + wm * 32 + tm * 16 + g;
                if (m0 < M) {
                    float2 v = make_float2(acc_i[tm][tn][0] + acc_h[tm][tn][0] + b2.x,
                                           acc_i[tm][tn][1] + acc_h[tm][tn][1] + b2.y);
                    *(float2*)&srz[(size_t)m0 * 256 + ng] = v;
                }
                if (m0 + 8 < M) {
                    float2 v = make_float2(acc_i[tm][tn][2] + acc_h[tm][tn][2] + b2.x,
                                           acc_i[tm][tn][3] + acc_h[tm][tn][3] + b2.y);
                    *(float2*)&srz[(size_t)(m0 + 8) * 256 + ng] = v;
                }
            }
        }
    } else {                                 // n gate: write i_n, h_n separately
        #pragma unroll
        for (int tn = 0; tn < 4; tn++) {
            int cl = wn * 32 + tn * 8 + q * 2;     // 0..127
            int ng = 256 + cl;
            float2 bi2 = *(const float2*)&bih[ng];
            float2 bh2 = *(const float2*)&bhh[ng];
            #pragma unroll
            for (int tm = 0; tm < 2; tm++) {
                int m0 = bm + wm * 32 + tm * 16 + g;
                if (m0 < M) {
                    *(float2*)&gin[(size_t)m0 * 128 + cl] =
                        make_float2(acc_i[tm][tn][0] + bi2.x, acc_i[tm][tn][1] + bi2.y);
                    *(float2*)&ghn[(size_t)m0 * 128 + cl] =
                        make_float2(acc_h[tm][tn][0] + bh2.x, acc_h[tm][tn][1] + bh2.y);
                }
                if (m0 + 8 < M) {
                    *(float2*)&gin[(size_t)(m0 + 8) * 128 + cl] =
                        make_float2(acc_i[tm][tn][2] + bi2.x, acc_i[tm][tn][3] + bi2.y);
                    *(float2*)&ghn[(size_t)(m0 + 8) * 128 + cl] =
                        make_float2(acc_h[tm][tn][2] + bh2.x, acc_h[tm][tn][3] + bh2.y);
                }
            }
        }
    }
}

// ---------------- GRU elementwise update ------------------------------------
__global__ void gru_update() {
    int idx = blockIdx.x * blockDim.x + threadIdx.x;
    if (idx >= NN * 32) return;
    int n = idx >> 5, c = idx & 31;
    const float* srz = d_srz + (size_t)n * 256;
    float4 sr = *(const float4*)&srz[c * 4];
    float4 sz = *(const float4*)&srz[128 + c * 4];
    float4 gn = *(const float4*)&d_gin[(size_t)n * 128 + c * 4];
    float4 hn = *(const float4*)&d_ghn[(size_t)n * 128 + c * 4];
    float4 h  = h_rec(&d_hhi[(size_t)n * 64 + c * 2], &d_hlo[(size_t)n * 64 + c * 2]);
    float4 o;
    { float r = sigm(sr.x), z = sigm(sz.x);
      float t = tanh_fast(fmaf(r, hn.x, gn.x)); o.x = fmaf(z, h.x - t, t); }
    { float r = sigm(sr.y), z = sigm(sz.y);
      float t = tanh_fast(fmaf(r, hn.y, gn.y)); o.y = fmaf(z, h.y - t, t); }
    { float r = sigm(sr.z), z = sigm(sz.z);
      float t = tanh_fast(fmaf(r, hn.z, gn.z)); o.z = fmaf(z, h.z - t, t); }
    { float r = sigm(sr.w), z = sigm(sz.w);
      float t = tanh_fast(fmaf(r, hn.w, gn.w)); o.w = fmaf(z, h.w - t, t); }
    split_store(o, &d_hhi[(size_t)n * 64 + c * 2], &d_hlo[(size_t)n * 64 + c * 2]);
}

// ---------------- gmax init + atomic max ------------------------------------
__global__ void init_gmax() {
    int idx = blockIdx.x * blockDim.x + threadIdx.x;
    if (idx >= NG * H) return;
    ((unsigned int*)d_gmax)[idx] = 0xFF800000u;
}
__device__ __forceinline__ void atomicMaxF(float* addr, float val) {
    if (val >= 0.f)
        atomicMax((int*)addr, __float_as_int(val));
    else
        atomicMin((unsigned int*)addr, __float_as_uint(val));
}

// ---------------- fused dense GEMM + segment max (BM=128, BN=64, 256 thr) ----
#define OFF_AHI  0
#define OFF_ALO  32768
#define OFF_BHI  65536
#define OFF_BLO  81920
#define GEMM_SMEM 98304

__device__ __forceinline__ void tile_load(uint32_t sb, char* smem,
    const __nv_bfloat16* __restrict__ Ahi, const __nv_bfloat16* __restrict__ Alo,
    const __nv_bfloat16* __restrict__ Whi, const __nv_bfloat16* __restrict__ Wlo,
    int bm, int bn, int M, int tid)
{
    #pragma unroll
    for (int it = 0; it < 8; it++) {
        int p = tid + it * 256;
        int row = p >> 4, c8 = p & 15;
        uint32_t off = row * 256 + ((c8 ^ (row & 7)) << 4);
        int m = bm + row;
        if (m < M) {
            CP16(sb + OFF_AHI + off, Ahi + (size_t)m * 128 + c8 * 8);
            CP16(sb + OFF_ALO + off, Alo + (size_t)m * 128 + c8 * 8);
        } else {
            *(uint4*)(smem + OFF_AHI + off) = make_uint4(0, 0, 0, 0);
            *(uint4*)(smem + OFF_ALO + off) = make_uint4(0, 0, 0, 0);
        }
    }
    #pragma unroll
    for (int it = 0; it < 4; it++) {
        int p = tid + it * 256;
        int row = p >> 4, c8 = p & 15;
        uint32_t off = row * 256 + ((c8 ^ (row & 7)) << 4);
        CP16(sb + OFF_BHI + off, Whi + (size_t)(bn + row) * 128 + c8 * 8);
        CP16(sb + OFF_BLO + off, Wlo + (size_t)(bn + row) * 128 + c8 * 8);
    }
    CP_COMMIT;
    CP_WAIT0;
}

__device__ __forceinline__ void tile_compute(uint32_t sb, float acc[2][4][4],
                                             int wm, int wn, int lrow, int lc)
{
    #pragma unroll
    for (int ks = 0; ks < 8; ks++) {
        const int cidx = 2 * ks + lc;
        uint32_t ah[2][4], al[2][4], bh[2][4], bl[2][4];
        #pragma unroll
        for (int tm = 0; tm < 2; tm++) {
            int r = wm * 32 + tm * 16 + lrow;
            uint32_t off = r * 256 + ((cidx ^ (r & 7)) << 4);
            LDSM_X4(ah[tm][0], ah[tm][1], ah[tm][2], ah[tm][3], sb + OFF_AHI + off);
            LDSM_X4(al[tm][0], al[tm][1], al[tm][2], al[tm][3], sb + OFF_ALO + off);
        }
        #pragma unroll
        for (int u = 0; u < 2; u++) {
            int r = wn * 32 + u * 16 + lrow;
            uint32_t off = r * 256 + ((cidx ^ (r & 7)) << 4);
            LDSM_X4(bh[u][0], bh[u][1], bh[u][2], bh[u][3], sb + OFF_BHI + off);
            LDSM_X4(bl[u][0], bl[u][1], bl[u][2], bl[u][3], sb + OFF_BLO + off);
        }
        #pragma unroll
        for (int tm = 0; tm < 2; tm++)
            #pragma unroll
            for (int tn = 0; tn < 4; tn++) {
                int u = tn >> 1, s = tn & 1;
                MMA_BF16(acc[tm][tn], ah[tm][0], ah[tm][1], ah[tm][2], ah[tm][3],
                         bh[u][s], bh[u][2 + s]);
                MMA_BF16(acc[tm][tn], ah[tm][0], ah[tm][1], ah[tm][2], ah[tm][3],
                         bl[u][s], bl[u][2 + s]);
                MMA_BF16(acc[tm][tn], al[tm][0], al[tm][1], al[tm][2], al[tm][3],
                         bh[u][s], bh[u][2 + s]);
            }
    }
}

__global__ void __launch_bounds__(256, 2)
dense_segmax(const __nv_bfloat16* __restrict__ Ahi, const __nv_bfloat16* __restrict__ Alo,
             const __nv_bfloat16* __restrict__ Whi, const __nv_bfloat16* __restrict__ Wlo,
             const float* __restrict__ bias, const int* __restrict__ batch, int M)
{
    extern __shared__ char smem[];
    const uint32_t sb = smem_u32(smem);
    const int tid = threadIdx.x, wid = tid >> 5, lane = tid & 31;
    const int bm = blockIdx.x * 128, bn = blockIdx.y * 64;
    const int wm = wid & 3, wn = wid >> 2;
    const int lrow = lane & 15, lc = lane >> 4;

    float acc[2][4][4];
    #pragma unroll
    for (int i = 0; i < 2; i++)
        #pragma unroll
        for (int j = 0; j < 4; j++)
            #pragma unroll
            for (int q = 0; q < 4; q++) acc[i][j][q] = 0.f;

    tile_load(sb, smem, Ahi, Alo, Whi, Wlo, bm, bn, M, tid);
    __syncthreads();
    tile_compute(sb, acc, wm, wn, lrow, lc);
    __syncthreads();                         // smem now dead -> reuse for staging

    float* sd = (float*)smem;                // [128][68]
    int* sbatch = (int*)(smem + OFF_BHI);    // [128]
    if (tid < 128) sbatch[tid] = __ldg(&batch[min(bm + tid, M - 1)]);

    const int g = lane >> 2, q = lane & 3;
    #pragma unroll
    for (int tn = 0; tn < 4; tn++) {
        int cl = wn * 32 + tn * 8 + q * 2;
        float2 b2 = *(const float2*)&bias[bn + cl];
        #pragma unroll
        for (int tm = 0; tm < 2; tm++) {
            int r0 = wm * 32 + tm * 16 + g;
            bool v0 = (bm + r0 < M), v1 = (bm + r0 + 8 < M);
            sd[r0 * 68 + cl]           = v0 ? acc[tm][tn][0] + b2.x : NEG_INF;
            sd[r0 * 68 + cl + 1]       = v0 ? acc[tm][tn][1] + b2.y : NEG_INF;
            sd[(r0 + 8) * 68 + cl]     = v1 ? acc[tm][tn][2] + b2.x : NEG_INF;
            sd[(r0 + 8) * 68 + cl + 1] = v1 ? acc[tm][tn][3] + b2.y : NEG_INF;
        }
    }
    __syncthreads();

    // segmented max over 32-row strips (batch is sorted)
    int col = tid & 63, r0 = (tid >> 6) * 32;
    int gcur = sbatch[r0];
    float mv = NEG_INF;
    #pragma unroll 8
    for (int r = r0; r < r0 + 32; r++) {
        int gnext = sbatch[r];
        if (gnext != gcur) {
            atomicMaxF(&d_gmax[(size_t)gcur * H + bn + col], mv);
            gcur = gnext;
            mv = NEG_INF;
        }
        mv = fmaxf(mv, sd[r * 68 + col]);
    }
    atomicMaxF(&d_gmax[(size_t)gcur * H + bn + col], mv);
}

// ---------------- classifier -------------------------------------------------
__global__ void classify(const float* __restrict__ clfW,
                         const float* __restrict__ clfb,
                         float* __restrict__ out) {
    __shared__ float red[4];
    int g = blockIdx.x;
    int t = threadIdx.x;
    float v = d_gmax[(size_t)g * H + t] * clfW[t];
    #pragma unroll
    for (int o = 16; o > 0; o >>= 1) v += __shfl_down_sync(0xffffffffu, v, o);
    if ((t & 31) == 0) red[t >> 5] = v;
    __syncthreads();
    if (t == 0) {
        float s = red[0] + red[1] + red[2] + red[3] + clfb[0];
        out[g] = 1.f / (1.f + expf(-s));
    }
}

// ---------------- launch -----------------------------------------------------
extern "C" void kernel_launch(void* const* d_in, const int* in_sizes, int n_in,
                              void* d_out, int out_size) {
    const int*   x       = (const int*)d_in[0];
    const int*   ei      = (const int*)d_in[1];
    const int*   batch   = (const int*)d_in[2];
    const float* emb     = (const float*)d_in[3];
    const float* Wih0    = (const float*)d_in[4];
    const float* Whh0    = (const float*)d_in[5];
    const float* bih0    = (const float*)d_in[6];
    const float* bhh0    = (const float*)d_in[7];
    const float* Wih1    = (const float*)d_in[8];
    const float* Whh1    = (const float*)d_in[9];
    const float* bih1    = (const float*)d_in[10];
    const float* bhh1    = (const float*)d_in[11];
    const float* denseW  = (const float*)d_in[12];
    const float* denseB  = (const float*)d_in[13];
    const float* clfW    = (const float*)d_in[14];
    const float* clfB    = (const float*)d_in[15];
    float* out = (float*)d_out;

    cudaFuncSetAttribute(gemm_dual, cudaFuncAttributeMaxDynamicSharedMemorySize, DUAL_SMEM);
    cudaFuncSetAttribute(dense_segmax, cudaFuncAttributeMaxDynamicSharedMemorySize, GEMM_SMEM);

    __nv_bfloat16 *p_whi, *p_wlo;
    uint32_t *p_hhi, *p_hlo, *p_ahi, *p_alo;
    float *p_srz, *p_gin, *p_ghn;
    cudaGetSymbolAddress((void**)&p_whi, d_whi);
    cudaGetSymbolAddress((void**)&p_wlo, d_wlo);
    cudaGetSymbolAddress((void**)&p_hhi, d_hhi);
    cudaGetSymbolAddress((void**)&p_hlo, d_hlo);
    cudaGetSymbolAddress((void**)&p_ahi, d_ahi);
    cudaGetSymbolAddress((void**)&p_alo, d_alo);
    cudaGetSymbolAddress((void**)&p_srz, d_srz);
    cudaGetSymbolAddress((void**)&p_gin, d_gin);
    cudaGetSymbolAddress((void**)&p_ghn, d_ghn);

    const int T = 256;
    dim3 g_dual((NN + 127) / 128, 3);    // BN=128 -> 3 gate tiles
    dim3 g_dense((NN + 127) / 128, 2);

    conv_weights<<<(WROWS * 128 + T - 1) / T, T>>>(Wih0, Whh0, Wih1, Whh1, denseW);
    gather_embed<<<(NN * 32 + T - 1) / T, T>>>(x, emb);
    csr_zero<<<NB1, T>>>();
    csr_hist<<<(NE + T - 1) / T, T>>>(ei);
    csr_bsum<<<NB1, T>>>();
    csr_bscan<<<1, 512>>>();
    csr_write<<<NB1, T>>>();
    csr_fill<<<(NE + T - 1) / T, T>>>(ei);

    const int woff_ih[2] = {0, 768};
    const int woff_hh[2] = {384, 1152};
    const float* bih[2] = {bih0, bih1};
    const float* bhh[2] = {bhh0, bhh1};

    for (int layer = 0; layer < 2; layer++) {
        agg_gather<<<(NN * 32 + T - 1) / T, T>>>();
        gemm_dual<<<g_dual, 512, DUAL_SMEM>>>(
            (const __nv_bfloat16*)p_ahi, (const __nv_bfloat16*)p_alo,
            p_whi + (size_t)woff_ih[layer] * 128, p_wlo + (size_t)woff_ih[layer] * 128,
            (const __nv_bfloat16*)p_hhi, (const __nv_bfloat16*)p_hlo,
            p_whi + (size_t)woff_hh[layer] * 128, p_wlo + (size_t)woff_hh[layer] * 128,
            bih[layer], bhh[layer], p_srz, p_gin, p_ghn, NN);
        gru_update<<<(NN * 32 + T - 1) / T, T>>>();
    }

    init_gmax<<<(NG * H + T - 1) / T, T>>>();
    dense_segmax<<<g_dense, T, GEMM_SMEM>>>(
        (const __nv_bfloat16*)p_hhi, (const __nv_bfloat16*)p_hlo,
        p_whi + (size_t)1536 * 128, p_wlo + (size_t)1536 * 128,
        denseB, batch, NN);
    classify<<<NG, 128>>>(clfW, clfB, out);
}

// round 15
// speedup vs baseline: 1.5106x; 1.5106x over previous
#include <cuda_runtime.h>
#include <cuda_bf16.h>
#include <math.h>
#include <stdint.h>

#define NN 100000
#define NE 1600000
#define H  128
#define NG 128
#define NB1 391          // ceil(NN/256)

// ---------------- scratch (device globals) ----------------------------------
__device__ uint32_t d_hhi[(size_t)NN * 64];    // h as bf16 pairs (hi/lo split)
__device__ uint32_t d_hlo[(size_t)NN * 64];
__device__ uint32_t d_ahi[(size_t)NN * 64];    // agg hi/lo
__device__ uint32_t d_alo[(size_t)NN * 64];
__device__ float    d_srz[(size_t)NN * 256];   // i_r+h_r | i_z+h_z (biased)
__device__ float    d_gin[(size_t)NN * 128];   // i_n + bih_n
__device__ float    d_ghn[(size_t)NN * 128];   // h_n + bhh_n
__device__ float    d_gmax[(size_t)NG * H];
// CSR
__device__ int d_cnt[NN];
__device__ int d_rowptr[NN + 1];
__device__ int d_pos[NN];
__device__ int d_esrc[NE];
__device__ int d_bsum[512];
__device__ int d_boff[512];
// pre-split weights: rows 0-383 Wih0, 384-767 Whh0, 768-1151 Wih1,
// 1152-1535 Whh1, 1536-1663 dense
#define WROWS 1664
__device__ __nv_bfloat16 d_whi[(size_t)WROWS * 128];
__device__ __nv_bfloat16 d_wlo[(size_t)WROWS * 128];

// ---------------- helpers ----------------------------------------------------
__device__ __forceinline__ uint32_t smem_u32(const void* p) {
    uint32_t a;
    asm("{ .reg .u64 t; cvta.to.shared.u64 t, %1; cvt.u32.u64 %0, t; }"
        : "=r"(a) : "l"(p));
    return a;
}
#define LDSM_X4(r0, r1, r2, r3, addr)                                       \
    asm volatile("ldmatrix.sync.aligned.m8n8.x4.shared.b16 {%0,%1,%2,%3}, [%4];" \
        : "=r"(r0), "=r"(r1), "=r"(r2), "=r"(r3) : "r"(addr))
#define MMA_BF16(c, a0, a1, a2, a3, b0, b1)                                 \
    asm volatile("mma.sync.aligned.m16n8k16.row.col.f32.bf16.bf16.f32 "     \
        "{%0,%1,%2,%3}, {%4,%5,%6,%7}, {%8,%9}, {%0,%1,%2,%3};"             \
        : "+f"((c)[0]), "+f"((c)[1]), "+f"((c)[2]), "+f"((c)[3])            \
        : "r"(a0), "r"(a1), "r"(a2), "r"(a3), "r"(b0), "r"(b1))
#define CP16(dst, src)                                                      \
    asm volatile("cp.async.cg.shared.global [%0], [%1], 16;"                \
                 :: "r"(dst), "l"(src))
#define CP_COMMIT asm volatile("cp.async.commit_group;")
#define CP_WAIT0  asm volatile("cp.async.wait_group 0;" ::: "memory")
#define NEG_INF __int_as_float(0xFF800000)

__device__ __forceinline__ float sigm(float x) {
    return 1.f / (1.f + __expf(-x));
}
// tanh(x) = 1 - 2/(e^{2x}+1); exact saturation at +-inf, err ~1e-6
__device__ __forceinline__ float tanh_fast(float x) {
    float e = __expf(2.f * x);
    return 1.f - __fdividef(2.f, e + 1.f);
}

// split float4 -> bf16 hi/lo pairs
__device__ __forceinline__ void split_store(float4 a, uint32_t* hip, uint32_t* lop) {
    __nv_bfloat162 h01 = __floats2bfloat162_rn(a.x, a.y);
    float2 f01 = __bfloat1622float2(h01);
    __nv_bfloat162 l01 = __floats2bfloat162_rn(a.x - f01.x, a.y - f01.y);
    __nv_bfloat162 h23 = __floats2bfloat162_rn(a.z, a.w);
    float2 f23 = __bfloat1622float2(h23);
    __nv_bfloat162 l23 = __floats2bfloat162_rn(a.z - f23.x, a.w - f23.y);
    *(uint2*)hip = make_uint2(*(uint32_t*)&h01, *(uint32_t*)&h23);
    *(uint2*)lop = make_uint2(*(uint32_t*)&l01, *(uint32_t*)&l23);
}
// reconstruct 4 floats from hi/lo pairs
__device__ __forceinline__ float4 h_rec(const uint32_t* hip, const uint32_t* lop) {
    uint2 vh = *(const uint2*)hip;
    uint2 vl = *(const uint2*)lop;
    float2 h01 = __bfloat1622float2(*(__nv_bfloat162*)&vh.x);
    float2 h23 = __bfloat1622float2(*(__nv_bfloat162*)&vh.y);
    float2 l01 = __bfloat1622float2(*(__nv_bfloat162*)&vl.x);
    float2 l23 = __bfloat1622float2(*(__nv_bfloat162*)&vl.y);
    return make_float4(h01.x + l01.x, h01.y + l01.y, h23.x + l23.x, h23.y + l23.y);
}

// ---------------- weight pre-split ------------------------------------------
__global__ void conv_weights(const float* __restrict__ Wih0, const float* __restrict__ Whh0,
                             const float* __restrict__ Wih1, const float* __restrict__ Whh1,
                             const float* __restrict__ denseW) {
    int idx = blockIdx.x * blockDim.x + threadIdx.x;
    if (idx >= WROWS * 128) return;
    int row = idx >> 7, col = idx & 127;
    float v;
    if      (row < 384)  v = Wih0[row * 128 + col];
    else if (row < 768)  v = Whh0[(row - 384) * 128 + col];
    else if (row < 1152) v = Wih1[(row - 768) * 128 + col];
    else if (row < 1536) v = Whh1[(row - 1152) * 128 + col];
    else                 v = denseW[(row - 1536) * 128 + col];
    __nv_bfloat16 h = __float2bfloat16(v);
    d_whi[idx] = h;
    d_wlo[idx] = __float2bfloat16(v - __bfloat162float(h));
}

// ---------------- gather: h = emb[x] (split only) ---------------------------
__global__ void gather_embed(const int* __restrict__ x,
                             const float* __restrict__ emb) {
    int idx = blockIdx.x * blockDim.x + threadIdx.x;
    if (idx >= NN * 32) return;
    int n = idx >> 5, c = idx & 31;
    int tok = x[n];
    float4 v = *(const float4*)&emb[(size_t)tok * H + c * 4];
    split_store(v, &d_hhi[(size_t)n * 64 + c * 2], &d_hlo[(size_t)n * 64 + c * 2]);
}

// ---------------- CSR build --------------------------------------------------
__global__ void csr_zero() {
    int i = blockIdx.x * blockDim.x + threadIdx.x;
    if (i < NN) d_cnt[i] = 0;
}
__global__ void csr_hist(const int* __restrict__ ei) {
    int e = blockIdx.x * blockDim.x + threadIdx.x;
    if (e < NE) atomicAdd(&d_cnt[ei[NE + e]], 1);
}
__global__ void csr_bsum() {
    int tid = threadIdx.x, idx = blockIdx.x * 256 + tid;
    int v = (idx < NN) ? d_cnt[idx] : 0;
    #pragma unroll
    for (int o = 16; o > 0; o >>= 1) v += __shfl_down_sync(0xffffffffu, v, o);
    __shared__ int ws[8];
    if ((tid & 31) == 0) ws[tid >> 5] = v;
    __syncthreads();
    if (tid == 0) {
        int s = 0;
        #pragma unroll
        for (int i = 0; i < 8; i++) s += ws[i];
        d_bsum[blockIdx.x] = s;
    }
}
__global__ void csr_bscan() {
    __shared__ int s[512];
    int t = threadIdx.x;
    int v = (t < NB1) ? d_bsum[t] : 0;
    s[t] = v; __syncthreads();
    for (int o = 1; o < 512; o <<= 1) {
        int x = (t >= o) ? s[t - o] : 0;
        __syncthreads();
        s[t] += x;
        __syncthreads();
    }
    d_boff[t] = s[t] - v;
    if (t == 0) d_rowptr[NN] = NE;
}
__global__ void csr_write() {
    int tid = threadIdx.x, lane = tid & 31, wid = tid >> 5;
    int idx = blockIdx.x * 256 + tid;
    int v = (idx < NN) ? d_cnt[idx] : 0;
    int incl = v;
    #pragma unroll
    for (int o = 1; o < 32; o <<= 1) {
        int y = __shfl_up_sync(0xffffffffu, incl, o);
        if (lane >= o) incl += y;
    }
    __shared__ int ws[8];
    if (lane == 31) ws[wid] = incl;
    __syncthreads();
    if (tid < 8) {
        int x = ws[tid];
        #pragma unroll
        for (int o = 1; o < 8; o <<= 1) {
            int y = __shfl_up_sync(0xffu, x, o);
            if (tid >= o) x += y;
        }
        ws[tid] = x;
    }
    __syncthreads();
    int base = d_boff[blockIdx.x] + (wid ? ws[wid - 1] : 0);
    int excl = base + incl - v;
    if (idx < NN) { d_rowptr[idx] = excl; d_pos[idx] = excl; }
}
__global__ void csr_fill(const int* __restrict__ ei) {
    int e = blockIdx.x * blockDim.x + threadIdx.x;
    if (e >= NE) return;
    int dst = ei[NE + e];
    int p = atomicAdd(&d_pos[dst], 1);
    d_esrc[p] = ei[e];
}

// ---------------- agg = segment_sum(h[src]) -> bf16 hi/lo -------------------
__global__ void agg_gather() {          // one warp per node
    int gw = (blockIdx.x * blockDim.x + threadIdx.x) >> 5;
    if (gw >= NN) return;
    int lane = threadIdx.x & 31;
    int beg = d_rowptr[gw], end = d_rowptr[gw + 1];
    float4 a0 = make_float4(0.f, 0.f, 0.f, 0.f);
    float4 a1 = make_float4(0.f, 0.f, 0.f, 0.f);
    int i = beg;
    for (; i + 1 < end; i += 2) {
        int s0 = __ldg(&d_esrc[i]), s1 = __ldg(&d_esrc[i + 1]);
        float4 v0 = h_rec(&d_hhi[(size_t)s0 * 64 + lane * 2], &d_hlo[(size_t)s0 * 64 + lane * 2]);
        float4 v1 = h_rec(&d_hhi[(size_t)s1 * 64 + lane * 2], &d_hlo[(size_t)s1 * 64 + lane * 2]);
        a0.x += v0.x; a0.y += v0.y; a0.z += v0.z; a0.w += v0.w;
        a1.x += v1.x; a1.y += v1.y; a1.z += v1.z; a1.w += v1.w;
    }
    if (i < end) {
        int s0 = __ldg(&d_esrc[i]);
        float4 v0 = h_rec(&d_hhi[(size_t)s0 * 64 + lane * 2], &d_hlo[(size_t)s0 * 64 + lane * 2]);
        a0.x += v0.x; a0.y += v0.y; a0.z += v0.z; a0.w += v0.w;
    }
    a0.x += a1.x; a0.y += a1.y; a0.z += a1.z; a0.w += a1.w;
    split_store(a0, &d_ahi[(size_t)gw * 64 + lane * 2], &d_alo[(size_t)gw * 64 + lane * 2]);
}

// ---------------- GEMM tile machinery (BM=128, BN=64, K=128 resident) -------
#define OFF_AHI  0
#define OFF_ALO  32768
#define OFF_BHI  65536
#define OFF_BLO  81920
#define GEMM_SMEM 98304

__device__ __forceinline__ void tile_load(uint32_t sb, char* smem,
    const __nv_bfloat16* __restrict__ Ahi, const __nv_bfloat16* __restrict__ Alo,
    const __nv_bfloat16* __restrict__ Whi, const __nv_bfloat16* __restrict__ Wlo,
    int bm, int bn, int M, int tid)
{
    #pragma unroll
    for (int it = 0; it < 8; it++) {
        int p = tid + it * 256;
        int row = p >> 4, c8 = p & 15;
        uint32_t off = row * 256 + ((c8 ^ (row & 7)) << 4);
        int m = bm + row;
        if (m < M) {
            CP16(sb + OFF_AHI + off, Ahi + (size_t)m * 128 + c8 * 8);
            CP16(sb + OFF_ALO + off, Alo + (size_t)m * 128 + c8 * 8);
        } else {
            *(uint4*)(smem + OFF_AHI + off) = make_uint4(0, 0, 0, 0);
            *(uint4*)(smem + OFF_ALO + off) = make_uint4(0, 0, 0, 0);
        }
    }
    #pragma unroll
    for (int it = 0; it < 4; it++) {
        int p = tid + it * 256;
        int row = p >> 4, c8 = p & 15;
        uint32_t off = row * 256 + ((c8 ^ (row & 7)) << 4);
        CP16(sb + OFF_BHI + off, Whi + (size_t)(bn + row) * 128 + c8 * 8);
        CP16(sb + OFF_BLO + off, Wlo + (size_t)(bn + row) * 128 + c8 * 8);
    }
    CP_COMMIT;
    CP_WAIT0;
}

__device__ __forceinline__ void tile_compute(uint32_t sb, float acc[2][4][4],
                                             int wm, int wn, int lrow, int lc)
{
    #pragma unroll
    for (int ks = 0; ks < 8; ks++) {
        const int cidx = 2 * ks + lc;
        uint32_t ah[2][4], al[2][4], bh[2][4], bl[2][4];
        #pragma unroll
        for (int tm = 0; tm < 2; tm++) {
            int r = wm * 32 + tm * 16 + lrow;
            uint32_t off = r * 256 + ((cidx ^ (r & 7)) << 4);
            LDSM_X4(ah[tm][0], ah[tm][1], ah[tm][2], ah[tm][3], sb + OFF_AHI + off);
            LDSM_X4(al[tm][0], al[tm][1], al[tm][2], al[tm][3], sb + OFF_ALO + off);
        }
        #pragma unroll
        for (int u = 0; u < 2; u++) {
            int r = wn * 32 + u * 16 + lrow;
            uint32_t off = r * 256 + ((cidx ^ (r & 7)) << 4);
            LDSM_X4(bh[u][0], bh[u][1], bh[u][2], bh[u][3], sb + OFF_BHI + off);
            LDSM_X4(bl[u][0], bl[u][1], bl[u][2], bl[u][3], sb + OFF_BLO + off);
        }
        #pragma unroll
        for (int tm = 0; tm < 2; tm++)
            #pragma unroll
            for (int tn = 0; tn < 4; tn++) {
                int u = tn >> 1, s = tn & 1;
                MMA_BF16(acc[tm][tn], ah[tm][0], ah[tm][1], ah[tm][2], ah[tm][3],
                         bh[u][s], bh[u][2 + s]);
                MMA_BF16(acc[tm][tn], ah[tm][0], ah[tm][1], ah[tm][2], ah[tm][3],
                         bl[u][s], bl[u][2 + s]);
                MMA_BF16(acc[tm][tn], al[tm][0], al[tm][1], al[tm][2], al[tm][3],
                         bh[u][s], bh[u][2 + s]);
            }
    }
}

// ---------------- fused dual GEMM: gi-tile + gh-tile per CTA ----------------
__global__ void __launch_bounds__(256, 2)
gemm_dual(const __nv_bfloat16* __restrict__ Aihi, const __nv_bfloat16* __restrict__ Ailo,
          const __nv_bfloat16* __restrict__ Wihi, const __nv_bfloat16* __restrict__ Wilo,
          const __nv_bfloat16* __restrict__ Ahhi, const __nv_bfloat16* __restrict__ Ahlo,
          const __nv_bfloat16* __restrict__ Whhi, const __nv_bfloat16* __restrict__ Whlo,
          const float* __restrict__ bih, const float* __restrict__ bhh,
          float* __restrict__ srz, float* __restrict__ gin, float* __restrict__ ghn,
          int M)
{
    extern __shared__ char smem[];
    const uint32_t sb = smem_u32(smem);
    const int tid = threadIdx.x, wid = tid >> 5, lane = tid & 31;
    const int bm = blockIdx.x * 128;
    const int bt = blockIdx.y, bn = bt * 64;
    const int wm = wid & 3, wn = wid >> 2;
    const int lrow = lane & 15, lc = lane >> 4;

    float acc_i[2][4][4], acc_h[2][4][4];
    #pragma unroll
    for (int i = 0; i < 2; i++)
        #pragma unroll
        for (int j = 0; j < 4; j++)
            #pragma unroll
            for (int q = 0; q < 4; q++) { acc_i[i][j][q] = 0.f; acc_h[i][j][q] = 0.f; }

    tile_load(sb, smem, Aihi, Ailo, Wihi, Wilo, bm, bn, M, tid);
    __syncthreads();
    tile_compute(sb, acc_i, wm, wn, lrow, lc);
    __syncthreads();                         // everyone done reading phase-0 smem
    tile_load(sb, smem, Ahhi, Ahlo, Whhi, Whlo, bm, bn, M, tid);
    __syncthreads();
    tile_compute(sb, acc_h, wm, wn, lrow, lc);

    // ---- epilogue ----
    const int g = lane >> 2, q = lane & 3;
    if (bt < 4) {                            // r/z gates: write summed
        #pragma unroll
        for (int tn = 0; tn < 4; tn++) {
            int n = bn + wn * 32 + tn * 8 + q * 2;
            float2 b2 = make_float2(bih[n] + bhh[n], bih[n + 1] + bhh[n + 1]);
            #pragma unroll
            for (int tm = 0; tm < 2; tm++) {
                int m0 = bm + wm * 32 + tm * 16 + g;
                if (m0 < M) {
                    float2 v = make_float2(acc_i[tm][tn][0] + acc_h[tm][tn][0] + b2.x,
                                           acc_i[tm][tn][1] + acc_h[tm][tn][1] + b2.y);
                    *(float2*)&srz[(size_t)m0 * 256 + n] = v;
                }
                if (m0 + 8 < M) {
                    float2 v = make_float2(acc_i[tm][tn][2] + acc_h[tm][tn][2] + b2.x,
                                           acc_i[tm][tn][3] + acc_h[tm][tn][3] + b2.y);
                    *(float2*)&srz[(size_t)(m0 + 8) * 256 + n] = v;
                }
            }
        }
    } else {                                 // n gate: write i_n, h_n separately
        int nb = bn - 256;
        #pragma unroll
        for (int tn = 0; tn < 4; tn++) {
            int cl = wn * 32 + tn * 8 + q * 2;
            int ngl = bn + cl;
            float2 bi2 = *(const float2*)&bih[ngl];
            float2 bh2 = *(const float2*)&bhh[ngl];
            #pragma unroll
            for (int tm = 0; tm < 2; tm++) {
                int m0 = bm + wm * 32 + tm * 16 + g;
                if (m0 < M) {
                    *(float2*)&gin[(size_t)m0 * 128 + nb + cl] =
                        make_float2(acc_i[tm][tn][0] + bi2.x, acc_i[tm][tn][1] + bi2.y);
                    *(float2*)&ghn[(size_t)m0 * 128 + nb + cl] =
                        make_float2(acc_h[tm][tn][0] + bh2.x, acc_h[tm][tn][1] + bh2.y);
                }
                if (m0 + 8 < M) {
                    *(float2*)&gin[(size_t)(m0 + 8) * 128 + nb + cl] =
                        make_float2(acc_i[tm][tn][2] + bi2.x, acc_i[tm][tn][3] + bi2.y);
                    *(float2*)&ghn[(size_t)(m0 + 8) * 128 + nb + cl] =
                        make_float2(acc_h[tm][tn][2] + bh2.x, acc_h[tm][tn][3] + bh2.y);
                }
            }
        }
    }
}

// ---------------- GRU elementwise update ------------------------------------
__global__ void gru_update() {
    int idx = blockIdx.x * blockDim.x + threadIdx.x;
    if (idx >= NN * 32) return;
    int n = idx >> 5, c = idx & 31;
    const float* srz = d_srz + (size_t)n * 256;
    float4 sr = *(const float4*)&srz[c * 4];
    float4 sz = *(const float4*)&srz[128 + c * 4];
    float4 gn = *(const float4*)&d_gin[(size_t)n * 128 + c * 4];
    float4 hn = *(const float4*)&d_ghn[(size_t)n * 128 + c * 4];
    float4 h  = h_rec(&d_hhi[(size_t)n * 64 + c * 2], &d_hlo[(size_t)n * 64 + c * 2]);
    float4 o;
    { float r = sigm(sr.x), z = sigm(sz.x);
      float t = tanh_fast(fmaf(r, hn.x, gn.x)); o.x = fmaf(z, h.x - t, t); }
    { float r = sigm(sr.y), z = sigm(sz.y);
      float t = tanh_fast(fmaf(r, hn.y, gn.y)); o.y = fmaf(z, h.y - t, t); }
    { float r = sigm(sr.z), z = sigm(sz.z);
      float t = tanh_fast(fmaf(r, hn.z, gn.z)); o.z = fmaf(z, h.z - t, t); }
    { float r = sigm(sr.w), z = sigm(sz.w);
      float t = tanh_fast(fmaf(r, hn.w, gn.w)); o.w = fmaf(z, h.w - t, t); }
    split_store(o, &d_hhi[(size_t)n * 64 + c * 2], &d_hlo[(size_t)n * 64 + c * 2]);
}

// ---------------- gmax init + atomic max ------------------------------------
__global__ void init_gmax() {
    int idx = blockIdx.x * blockDim.x + threadIdx.x;
    if (idx >= NG * H) return;
    ((unsigned int*)d_gmax)[idx] = 0xFF800000u;
}
__device__ __forceinline__ void atomicMaxF(float* addr, float val) {
    if (val >= 0.f)
        atomicMax((int*)addr, __float_as_int(val));
    else
        atomicMin((unsigned int*)addr, __float_as_uint(val));
}

// ---------------- fused dense GEMM + segment max -----------------------------
__global__ void __launch_bounds__(256, 2)
dense_segmax(const __nv_bfloat16* __restrict__ Ahi, const __nv_bfloat16* __restrict__ Alo,
             const __nv_bfloat16* __restrict__ Whi, const __nv_bfloat16* __restrict__ Wlo,
             const float* __restrict__ bias, const int* __restrict__ batch, int M)
{
    extern __shared__ char smem[];
    const uint32_t sb = smem_u32(smem);
    const int tid = threadIdx.x, wid = tid >> 5, lane = tid & 31;
    const int bm = blockIdx.x * 128, bn = blockIdx.y * 64;
    const int wm = wid & 3, wn = wid >> 2;
    const int lrow = lane & 15, lc = lane >> 4;

    float acc[2][4][4];
    #pragma unroll
    for (int i = 0; i < 2; i++)
        #pragma unroll
        for (int j = 0; j < 4; j++)
            #pragma unroll
            for (int q = 0; q < 4; q++) acc[i][j][q] = 0.f;

    tile_load(sb, smem, Ahi, Alo, Whi, Wlo, bm, bn, M, tid);
    __syncthreads();
    tile_compute(sb, acc, wm, wn, lrow, lc);
    __syncthreads();                         // smem now dead -> reuse for staging

    float* sd = (float*)smem;                // [128][68]
    int* sbatch = (int*)(smem + OFF_BHI);    // [128]
    if (tid < 128) sbatch[tid] = __ldg(&batch[min(bm + tid, M - 1)]);

    const int g = lane >> 2, q = lane & 3;
    #pragma unroll
    for (int tn = 0; tn < 4; tn++) {
        int cl = wn * 32 + tn * 8 + q * 2;
        float2 b2 = *(const float2*)&bias[bn + cl];
        #pragma unroll
        for (int tm = 0; tm < 2; tm++) {
            int r0 = wm * 32 + tm * 16 + g;
            bool v0 = (bm + r0 < M), v1 = (bm + r0 + 8 < M);
            sd[r0 * 68 + cl]           = v0 ? acc[tm][tn][0] + b2.x : NEG_INF;
            sd[r0 * 68 + cl + 1]       = v0 ? acc[tm][tn][1] + b2.y : NEG_INF;
            sd[(r0 + 8) * 68 + cl]     = v1 ? acc[tm][tn][2] + b2.x : NEG_INF;
            sd[(r0 + 8) * 68 + cl + 1] = v1 ? acc[tm][tn][3] + b2.y : NEG_INF;
        }
    }
    __syncthreads();

    // segmented max over 32-row strips (batch is sorted)
    int col = tid & 63, r0 = (tid >> 6) * 32;
    int gcur = sbatch[r0];
    float mv = NEG_INF;
    #pragma unroll 8
    for (int r = r0; r < r0 + 32; r++) {
        int gnext = sbatch[r];
        if (gnext != gcur) {
            atomicMaxF(&d_gmax[(size_t)gcur * H + bn + col], mv);
            gcur = gnext;
            mv = NEG_INF;
        }
        mv = fmaxf(mv, sd[r * 68 + col]);
    }
    atomicMaxF(&d_gmax[(size_t)gcur * H + bn + col], mv);
}

// ---------------- classifier -------------------------------------------------
__global__ void classify(const float* __restrict__ clfW,
                         const float* __restrict__ clfb,
                         float* __restrict__ out) {
    __shared__ float red[4];
    int g = blockIdx.x;
    int t = threadIdx.x;
    float v = d_gmax[(size_t)g * H + t] * clfW[t];
    #pragma unroll
    for (int o = 16; o > 0; o >>= 1) v += __shfl_down_sync(0xffffffffu, v, o);
    if ((t & 31) == 0) red[t >> 5] = v;
    __syncthreads();
    if (t == 0) {
        float s = red[0] + red[1] + red[2] + red[3] + clfb[0];
        out[g] = 1.f / (1.f + expf(-s));
    }
}

// ---------------- launch -----------------------------------------------------
extern "C" void kernel_launch(void* const* d_in, const int* in_sizes, int n_in,
                              void* d_out, int out_size) {
    const int*   x       = (const int*)d_in[0];
    const int*   ei      = (const int*)d_in[1];
    const int*   batch   = (const int*)d_in[2];
    const float* emb     = (const float*)d_in[3];
    const float* Wih0    = (const float*)d_in[4];
    const float* Whh0    = (const float*)d_in[5];
    const float* bih0    = (const float*)d_in[6];
    const float* bhh0    = (const float*)d_in[7];
    const float* Wih1    = (const float*)d_in[8];
    const float* Whh1    = (const float*)d_in[9];
    const float* bih1    = (const float*)d_in[10];
    const float* bhh1    = (const float*)d_in[11];
    const float* denseW  = (const float*)d_in[12];
    const float* denseB  = (const float*)d_in[13];
    const float* clfW    = (const float*)d_in[14];
    const float* clfB    = (const float*)d_in[15];
    float* out = (float*)d_out;

    cudaFuncSetAttribute(gemm_dual, cudaFuncAttributeMaxDynamicSharedMemorySize, GEMM_SMEM);
    cudaFuncSetAttribute(dense_segmax, cudaFuncAttributeMaxDynamicSharedMemorySize, GEMM_SMEM);

    __nv_bfloat16 *p_whi, *p_wlo;
    uint32_t *p_hhi, *p_hlo, *p_ahi, *p_alo;
    float *p_srz, *p_gin, *p_ghn;
    cudaGetSymbolAddress((void**)&p_whi, d_whi);
    cudaGetSymbolAddress((void**)&p_wlo, d_wlo);
    cudaGetSymbolAddress((void**)&p_hhi, d_hhi);
    cudaGetSymbolAddress((void**)&p_hlo, d_hlo);
    cudaGetSymbolAddress((void**)&p_ahi, d_ahi);
    cudaGetSymbolAddress((void**)&p_alo, d_alo);
    cudaGetSymbolAddress((void**)&p_srz, d_srz);
    cudaGetSymbolAddress((void**)&p_gin, d_gin);
    cudaGetSymbolAddress((void**)&p_ghn, d_ghn);

    const int T = 256;
    dim3 g_dual((NN + 127) / 128, 6);
    dim3 g_dense((NN + 127) / 128, 2);

    conv_weights<<<(WROWS * 128 + T - 1) / T, T>>>(Wih0, Whh0, Wih1, Whh1, denseW);
    gather_embed<<<(NN * 32 + T - 1) / T, T>>>(x, emb);
    csr_zero<<<NB1, T>>>();
    csr_hist<<<(NE + T - 1) / T, T>>>(ei);
    csr_bsum<<<NB1, T>>>();
    csr_bscan<<<1, 512>>>();
    csr_write<<<NB1, T>>>();
    csr_fill<<<(NE + T - 1) / T, T>>>(ei);

    const int woff_ih[2] = {0, 768};
    const int woff_hh[2] = {384, 1152};
    const float* bih[2] = {bih0, bih1};
    const float* bhh[2] = {bhh0, bhh1};

    for (int layer = 0; layer < 2; layer++) {
        agg_gather<<<(NN * 32 + T - 1) / T, T>>>();
        gemm_dual<<<g_dual, T, GEMM_SMEM>>>(
            (const __nv_bfloat16*)p_ahi, (const __nv_bfloat16*)p_alo,
            p_whi + (size_t)woff_ih[layer] * 128, p_wlo + (size_t)woff_ih[layer] * 128,
            (const __nv_bfloat16*)p_hhi, (const __nv_bfloat16*)p_hlo,
            p_whi + (size_t)woff_hh[layer] * 128, p_wlo + (size_t)woff_hh[layer] * 128,
            bih[layer], bhh[layer], p_srz, p_gin, p_ghn, NN);
        gru_update<<<(NN * 32 + T - 1) / T, T>>>();
    }

    init_gmax<<<(NG * H + T - 1) / T, T>>>();
    dense_segmax<<<g_dense, T, GEMM_SMEM>>>(
        (const __nv_bfloat16*)p_hhi, (const __nv_bfloat16*)p_hlo,
        p_whi + (size_t)1536 * 128, p_wlo + (size_t)1536 * 128,
        denseB, batch, NN);
    classify<<<NG, 128>>>(clfW, clfB, out);
}